// round 9
// baseline (speedup 1.0000x reference)
#include <cuda_runtime.h>
#include <cstdint>

// Kuramoto oscillators: B=32, N=2048, K=8, T=20.
// R9: NO clusters, NO smem data plane. The output tensor out[t] doubles as
// the phase-exchange buffer (written once at step t-1, read at step t; L1 is
// per-launch-flushed and lines are first-touched after the barrier, so plain
// cached LDG gathers are safe). 128 CTAs x 512 thr (4 CTAs per batch, 512
// oscillators each), all co-resident (128 < 148 SMs). Inter-step sync is the
// cooperative-groups grid.sync pattern: __syncthreads -> thread0
// atom.add.release.gpu on a per-step counter -> poll ld.acquire.gpu until a
// ticket-derived target -> __syncthreads. Tickets ((old & ~127)+128) make
// counters monotonic, so no reset is needed across graph replays.
// Step-0 gathers read phase0 directly (no prologue barrier).
// Gathered phases are unreduced; the DIFFERENCE is range-reduced to [-pi,pi]
// before __sinf (same accuracy as prior passing rounds).
// Duplicate scatter targets: LAST k wins; n = #distinct nonzero targets.
// eps/n folded into the weights (eps=1, anneal=0).

#define Nn 2048
#define Kk 8
#define Bb 32
#define Tt 20
#define CPB 4                       // CTAs per batch
#define THREADS 512
#define GRID (Bb * CPB)             // 128 CTAs
#define BN (Bb * Nn)                // 65536

#define TWO_PI     6.28318530717958647692f
#define INV_TWO_PI 0.15915494309189533577f

__device__ unsigned int g_ctr[32];  // per-step barrier counters (monotonic)

__device__ __forceinline__ unsigned int atom_add_release_gpu(unsigned int* p) {
    unsigned int old;
    asm volatile("atom.add.release.gpu.global.u32 %0, [%1], 1;"
                 : "=r"(old) : "l"(p) : "memory");
    return old;
}

__device__ __forceinline__ unsigned int ld_acquire_gpu(const unsigned int* p) {
    unsigned int v;
    asm volatile("ld.acquire.gpu.global.u32 %0, [%1];" : "=r"(v) : "l"(p) : "memory");
    return v;
}

__global__ void __launch_bounds__(THREADS, 1)
osc_kernel(const float* __restrict__ coupling,   // [B,N,K]
           const float* __restrict__ phase0,     // [B,N]
           const float* __restrict__ omega,      // [B,N]
           const int*   __restrict__ conn,       // [N,K]
           float*       __restrict__ out)        // [T+1,B,N]
{
    const int cid = blockIdx.x;
    const int b   = cid >> 2;                    // batch element
    const int tid = threadIdx.x;
    const int n   = ((cid & 3) << 9) | tid;      // oscillator 0..2047

    // ---- prologue: dedup couplings, fold eps/n into weights ----
    float w[Kk];
    int   off[Kk];
    int idx[Kk];
    #pragma unroll
    for (int k = 0; k < Kk; ++k) idx[k] = conn[n * Kk + k];

    int cnt = 0;
    #pragma unroll
    for (int k = 0; k < Kk; ++k) {
        bool win = true;
        #pragma unroll
        for (int k2 = k + 1; k2 < Kk; ++k2) win = win && (idx[k2] != idx[k]);
        const float c = coupling[((size_t)b * Nn + n) * Kk + k];
        w[k]   = win ? c : 0.0f;
        off[k] = idx[k];
        cnt += (win && (c != 0.0f)) ? 1 : 0;
    }
    const float inv = (cnt > 0) ? (1.0f / (float)cnt) : 0.0f;
    #pragma unroll
    for (int k = 0; k < Kk; ++k) w[k] *= inv;

    float p  = phase0[(size_t)b * Nn + n];
    const float om = omega[(size_t)b * Nn + n];
    out[(size_t)b * Nn + n] = p;                 // t=0 output slice

    // gather source for step 0 is the (complete) phase0 input row
    const float* __restrict__ src = phase0 + (size_t)b * Nn;

    // ---- time stepping ----
    #pragma unroll 1
    for (int t = 0; t < Tt; ++t) {
        // gather 8 neighbor phases (unreduced), L1-cached LDG
        float pm[Kk];
        #pragma unroll
        for (int k = 0; k < Kk; ++k) pm[k] = src[off[k]];

        float acc = 0.0f;
        #pragma unroll
        for (int k = 0; k < Kk; ++k) {
            float d = pm[k] - p;                          // unreduced diff
            d -= TWO_PI * rintf(d * INV_TWO_PI);          // reduce to [-pi,pi]
            acc += w[k] * __sinf(d);
        }

        p += acc + om;

        // publish new phase: out[t+1] is both output and next gather source
        float* dst = out + (size_t)(t + 1) * BN + (size_t)b * Nn;
        dst[n] = p;

        if (t < Tt - 1) {
            __syncthreads();                     // CTA's STGs all issued
            if (tid == 0) {
                const unsigned int old = atom_add_release_gpu(&g_ctr[t]);
                const unsigned int target = (old & ~127u) + 128u;
                while (ld_acquire_gpu(&g_ctr[t]) < target) { }
            }
            __syncthreads();                     // release the CTA
            src = dst;
        }
    }
}

extern "C" void kernel_launch(void* const* d_in, const int* in_sizes, int n_in,
                              void* d_out, int out_size)
{
    const float* coupling = (const float*)d_in[0];   // [B,N,K] f32
    const float* phase0   = (const float*)d_in[1];   // [B,N]   f32
    const float* omega    = (const float*)d_in[2];   // [B,N]   f32
    const int*   conn     = (const int*)  d_in[3];   // [N,K]   i32
    float*       out      = (float*)d_out;           // [T+1,B,N] f32

    osc_kernel<<<GRID, THREADS>>>(coupling, phase0, omega, conn, out);
}

// round 10
// speedup vs baseline: 1.9308x; 1.9308x over previous
#include <cuda_runtime.h>
#include <cstdint>

// Kuramoto oscillators: B=32, N=2048, K=8, T=20.
// R10: occupancy-paired clusters. 32 clusters x 8 CTAs (grid=256), 256
// threads/CTA, 256 oscillators/CTA, __launch_bounds__(256,2) -> 2 CTAs per
// SM (different clusters, via CLC contiguous placement + wave wrap). While
// one CTA sits in its DSMEM exchange tail, the co-resident CTA computes:
// R8's pipelining effect at full chip. Protocol identical to R4/R8: each of
// 7 threads pushes the CTA's 1KB slice to one peer (cp.async.bulk S2S with
// complete_tx on the peer's per-buffer mbarrier); expect = 7KB; CTA-scope
// acquire wait; barrier armed right after the wait (transient-negative tx is
// legal). Duplicate scatter targets: LAST k wins; n = #distinct nonzero.
// eps/n folded into the weights (eps=1, anneal=0).

#define Nn 2048
#define Kk 8
#define Bb 32
#define Tt 20
#define CSZ 8
#define THREADS 256
#define NPC (Nn / CSZ)                          // 256 oscillators per CTA
#define SLICE_BYTES (NPC * 4)                   // 1024 bytes per push
#define EXPECT_BYTES ((CSZ - 1) * SLICE_BYTES)  // 7168 remote bytes per step

#define TWO_PI     6.28318530717958647692f
#define INV_TWO_PI 0.15915494309189533577f

__device__ __forceinline__ uint32_t smem_u32(const void* p) {
    uint32_t a;
    asm("{ .reg .u64 t; cvta.to.shared.u64 t, %1; cvt.u32.u64 %0, t; }"
        : "=r"(a) : "l"(p));
    return a;
}

__device__ __forceinline__ uint32_t mapa_u32(uint32_t laddr, uint32_t rank) {
    uint32_t r;
    asm("mapa.shared::cluster.u32 %0, %1, %2;" : "=r"(r) : "r"(laddr), "r"(rank));
    return r;
}

__device__ __forceinline__ void mbar_init(uint32_t laddr, uint32_t count) {
    asm volatile("mbarrier.init.shared.b64 [%0], %1;" :: "r"(laddr), "r"(count) : "memory");
}

__device__ __forceinline__ void mbar_arrive_expect_tx(uint32_t laddr, uint32_t tx) {
    asm volatile("mbarrier.arrive.expect_tx.shared.b64 _, [%0], %1;"
                 :: "r"(laddr), "r"(tx) : "memory");
}

__device__ __forceinline__ void bulk_s2s_cluster(uint32_t dst_cluster,
                                                 uint32_t src_cta,
                                                 uint32_t bytes,
                                                 uint32_t rmbar_cluster) {
    asm volatile(
        "cp.async.bulk.shared::cluster.shared::cta.mbarrier::complete_tx::bytes "
        "[%0], [%1], %2, [%3];"
        :: "r"(dst_cluster), "r"(src_cta), "r"(bytes), "r"(rmbar_cluster)
        : "memory");
}

// CTA-scope acquire wait (validated in R8)
__device__ __forceinline__ void mbar_wait(uint32_t laddr, uint32_t parity) {
    uint32_t done;
    asm volatile(
        "{ .reg .pred p;\n"
        "  mbarrier.try_wait.parity.acquire.cta.shared::cta.b64 p, [%1], %2;\n"
        "  selp.b32 %0, 1, 0, p; }"
        : "=r"(done) : "r"(laddr), "r"(parity) : "memory");
    if (!done) {
        asm volatile(
            "{ .reg .pred p;\n"
            "WL_%=:\n"
            "  mbarrier.try_wait.parity.acquire.cta.shared::cta.b64 p, [%0], %1, 0x989680;\n"
            "  @p bra.uni WD_%=;\n"
            "  bra.uni WL_%=;\n"
            "WD_%=: }"
            :: "r"(laddr), "r"(parity) : "memory");
    }
}

__global__ void __launch_bounds__(THREADS, 2) __cluster_dims__(CSZ, 1, 1)
osc_kernel(const float* __restrict__ coupling,   // [B,N,K]
           const float* __restrict__ phase0,     // [B,N]
           const float* __restrict__ omega,      // [B,N]
           const int*   __restrict__ conn,       // [N,K]
           float*       __restrict__ out)        // [T+1,B,N]
{
    __shared__ __align__(16) float th[2][Nn];             // replicated phases
    __shared__ __align__(8)  unsigned long long mbar[2];  // one per buffer

    uint32_t rank;
    asm("mov.u32 %0, %%cluster_ctarank;" : "=r"(rank));
    const int b   = blockIdx.x / CSZ;            // batch element (cluster id)
    const int tid = threadIdx.x;
    const int n   = (int)rank * NPC + tid;       // this thread's oscillator

    const uint32_t mb_l0 = smem_u32(&mbar[0]);
    const uint32_t mb_l1 = smem_u32(&mbar[1]);
    if (tid == 0) {
        mbar_init(mb_l0, 1);   // 1 arrival (arming thread) + tx bytes
        mbar_init(mb_l1, 1);
    }

    // ---- prologue: dedup couplings, fold eps/n into weights ----
    float w[Kk];
    int   off[Kk];
    int idx[Kk];
    #pragma unroll
    for (int k = 0; k < Kk; ++k) idx[k] = conn[n * Kk + k];

    int cnt = 0;
    #pragma unroll
    for (int k = 0; k < Kk; ++k) {
        bool win = true;
        #pragma unroll
        for (int k2 = k + 1; k2 < Kk; ++k2) win = win && (idx[k2] != idx[k]);
        const float c = coupling[((size_t)b * Nn + n) * Kk + k];
        w[k]   = win ? c : 0.0f;
        off[k] = idx[k];
        cnt += (win && (c != 0.0f)) ? 1 : 0;
    }
    const float inv = (cnt > 0) ? (1.0f / (float)cnt) : 0.0f;
    #pragma unroll
    for (int k = 0; k < Kk; ++k) w[k] *= inv;

    float p  = phase0[(size_t)b * Nn + n];
    const float om = omega[(size_t)b * Nn + n];
    out[(size_t)b * Nn + n] = p;                 // t=0 slice

    // each CTA fills its FULL th[0] locally from gmem (8 per thread)
    #pragma unroll
    for (int j = 0; j < CSZ; ++j) {
        const int m  = tid + j * THREADS;
        const float q = phase0[(size_t)b * Nn + m];
        th[0][m] = q - TWO_PI * rintf(q * INV_TWO_PI);
    }
    float pr = p - TWO_PI * rintf(p * INV_TWO_PI);

    // hoisted push addresses (sender threads tid<7): peer slice dst + peer mbar
    const uint32_t peer = (tid < CSZ - 1)
        ? ((uint32_t)tid < rank ? (uint32_t)tid : (uint32_t)(tid + 1)) : 0u;
    const uint32_t src_l[2] = { smem_u32(&th[0][rank * NPC]),
                                smem_u32(&th[1][rank * NPC]) };
    uint32_t dst_r[2], mbr_r[2];
    if (tid < CSZ - 1) {
        dst_r[0] = mapa_u32(src_l[0], peer);
        dst_r[1] = mapa_u32(src_l[1], peer);
        mbr_r[0] = mapa_u32(mb_l0, peer);
        mbr_r[1] = mapa_u32(mb_l1, peer);
    }

    __syncthreads();   // th[0] + mbarrier init complete at CTA scope
    // cluster-wide: all mbarriers initialized before any peer bulk signals
    asm volatile("barrier.cluster.arrive.aligned;" ::: "memory");
    asm volatile("barrier.cluster.wait.aligned;"   ::: "memory");

    uint32_t par[2] = {0, 0};

    // ---- time stepping ----
    #pragma unroll 1
    for (int t = 0; t < Tt; ++t) {
        const int c  = t & 1;
        const int nb = c ^ 1;

        if (t > 0) {                 // all 7KB of buffer c arrived
            mbar_wait(c ? mb_l1 : mb_l0, par[c]);
            par[c] ^= 1u;
        }
        // arm next buffer's barrier early (transient-negative tx is legal)
        if (t < Tt - 1 && tid == 0)
            mbar_arrive_expect_tx(nb ? mb_l1 : mb_l0, EXPECT_BYTES);

        const float* __restrict__ cur = th[c];

        float acc = 0.0f;
        #pragma unroll
        for (int k = 0; k < Kk; ++k)
            acc += w[k] * __sinf(cur[off[k]] - pr);   // arg in [-2pi, 2pi]

        p += acc + om;
        const float prn = p - TWO_PI * rintf(p * INV_TWO_PI);
        pr = prn;

        // own slice + global output (STG overlaps everything)
        th[nb][n] = prn;
        out[(size_t)(t + 1) * (Bb * Nn) + (size_t)b * Nn + n] = p;

        if (t < Tt - 1) {
            __syncthreads();         // slice complete before engine reads it
            if (tid < CSZ - 1) {
                asm volatile("fence.proxy.async.shared::cta;" ::: "memory");
                bulk_s2s_cluster(dst_r[nb], src_l[nb], SLICE_BYTES, mbr_r[nb]);
            }
        }
    }
}

extern "C" void kernel_launch(void* const* d_in, const int* in_sizes, int n_in,
                              void* d_out, int out_size)
{
    const float* coupling = (const float*)d_in[0];   // [B,N,K] f32
    const float* phase0   = (const float*)d_in[1];   // [B,N]   f32
    const float* omega    = (const float*)d_in[2];   // [B,N]   f32
    const int*   conn     = (const int*)  d_in[3];   // [N,K]   i32
    float*       out      = (float*)d_out;           // [T+1,B,N] f32

    osc_kernel<<<Bb * CSZ, THREADS>>>(coupling, phase0, omega, conn, out);
}